// round 3
// baseline (speedup 1.0000x reference)
#include <cuda_runtime.h>

#define NN 2048
#define FF 64
#define KK 8
#define GROUP 32
#define NBUCK 4096
#define BSHIFT 20            // 32 - log2(NBUCK)
#define BPT (NBUCK / 256)    // buckets per thread in prep
#define WARMB 192            // adj L2-warm blocks

// Scratch: per-feature bucket-descending x values and node indices.
__device__ float g_sx[FF * NN];
__device__ int   g_si[FF * NN];

__device__ __forceinline__ unsigned key_of(float v) {
    unsigned u = __float_as_uint(v);
    return (u & 0x80000000u) ? ~u : (u | 0x80000000u);
}
__device__ __forceinline__ float val_of(unsigned k) {
    unsigned u = (k & 0x80000000u) ? (k ^ 0x80000000u) : ~k;
    return __uint_as_float(u);
}

// Blocks [0, FF): counting-sort feature f into descending-bucket order.
// Blocks [FF, FF+WARMB): stream-prefetch adj into L2 (concurrent warm).
__global__ __launch_bounds__(256) void prep_kernel(const float* __restrict__ x,
                                                   const float* __restrict__ adj) {
    const int tid = threadIdx.x;

    if (blockIdx.x >= FF) {
        // L2 warm: 16MB of adj, 128B lines.
        const size_t nlines = (size_t)NN * NN * sizeof(float) / 128;
        const size_t stride = (size_t)WARMB * 256;
        for (size_t i = (size_t)(blockIdx.x - FF) * 256 + tid; i < nlines; i += stride) {
            const char* p = (const char*)adj + i * 128;
            asm volatile("prefetch.global.L2 [%0];" :: "l"(p));
        }
        return;
    }

    const int f = blockIdx.x;
    __shared__ unsigned skey[NN];
    __shared__ int hist[NBUCK];
    __shared__ int tsum[256];

    for (int i = tid; i < NBUCK; i += 256) hist[i] = 0;
    __syncthreads();

    // Pass 1: keys + histogram.
    for (int i = tid; i < NN; i += 256) {
        float v = x[(size_t)i * FF + f];
        unsigned k = key_of(v);
        skey[i] = k;
        atomicAdd(&hist[k >> BSHIFT], 1);
    }
    __syncthreads();

    // Pass 2: descending-exclusive offsets (suffix scan).
    const int base = tid * BPT;
    int csum = 0;
    #pragma unroll
    for (int j = 0; j < BPT; j++) csum += hist[base + j];
    tsum[tid] = csum;
    __syncthreads();
    for (int d = 1; d < 256; d <<= 1) {     // inclusive suffix scan
        int v = tsum[tid] + ((tid + d < 256) ? tsum[tid + d] : 0);
        __syncthreads();
        tsum[tid] = v;
        __syncthreads();
    }
    int run = (tid < 255) ? tsum[tid + 1] : 0;   // elements in higher chunks
    #pragma unroll
    for (int j = BPT - 1; j >= 0; j--) {
        int c = hist[base + j];
        hist[base + j] = run;                    // start pos of bucket (descending)
        run += c;
    }
    __syncthreads();

    // Pass 3: scatter.
    for (int i = tid; i < NN; i += 256) {
        unsigned k = skey[i];
        int pos = atomicAdd(&hist[k >> BSHIFT], 1);
        g_si[f * NN + pos] = i;
        g_sx[f * NN + pos] = val_of(k);
    }
}

// blockIdx.y = f, blockIdx.x = m-tile. One thread per m, lanes coalesced over m,
// row index uniform across the warp. Top-8 in registers; stop when the 8th best
// t7 >= max(bucket_upper(x_cur), 0): adj in [0,1) so every remaining product
// <= max(x, 0) < bucket upper edge.
__global__ __launch_bounds__(128) void topk_kernel(const float* __restrict__ x,
                                                   const float* __restrict__ adj,
                                                   float* __restrict__ out) {
    __shared__ float s_x[NN + GROUP];
    __shared__ int   s_i[NN + GROUP];
    const int f = blockIdx.y;
    const int tid = threadIdx.x;
    const float NEG_INF = -__int_as_float(0x7f800000);

    for (int i = tid; i < NN; i += 128) {
        s_x[i] = g_sx[f * NN + i];
        s_i[i] = g_si[f * NN + i];
    }
    if (tid < GROUP) { s_x[NN + tid] = NEG_INF; s_i[NN + tid] = 0; }
    __syncthreads();

    const int m = blockIdx.x * 128 + tid;
    const float* adjm = adj + m;

    float t0 = NEG_INF, t1 = NEG_INF, t2 = NEG_INF, t3 = NEG_INF;
    float t4 = NEG_INF, t5 = NEG_INF, t6 = NEG_INF, t7 = NEG_INF;

    float pa[GROUP];
    #pragma unroll
    for (int u = 0; u < GROUP; u++)
        pa[u] = __ldg(adjm + (size_t)s_i[u] * NN);

    bool done = false;
    #pragma unroll 1
    for (int ib = 0; ib < NN; ib += GROUP) {
        if (!__ballot_sync(0xffffffffu, !done)) break;

        // Unconditional prefetch of next group: no dependence on `done`,
        // so the load stream pipelines ahead of the exit check.
        float na[GROUP];
        #pragma unroll
        for (int u = 0; u < GROUP; u++)
            na[u] = __ldg(adjm + (size_t)s_i[ib + GROUP + u] * NN);

        if (!done) {
            #pragma unroll
            for (int u = 0; u < GROUP; u++) {
                float c = pa[u] * s_x[ib + u];
                if (c > t7) {   // rare: sorted insert via max/min chain
                    float w;
                    w = fmaxf(t0, c); c = fminf(t0, c); t0 = w;
                    w = fmaxf(t1, c); c = fminf(t1, c); t1 = w;
                    w = fmaxf(t2, c); c = fminf(t2, c); t2 = w;
                    w = fmaxf(t3, c); c = fminf(t3, c); t3 = w;
                    w = fmaxf(t4, c); c = fminf(t4, c); t4 = w;
                    w = fmaxf(t5, c); c = fminf(t5, c); t5 = w;
                    w = fmaxf(t6, c); c = fminf(t6, c); t6 = w;
                    t7 = fmaxf(t7, c);
                }
            }
            // Bucket-conservative early stop: everything after this group is in
            // the same or a lower bucket than the group's last element.
            unsigned kl = key_of(s_x[ib + GROUP - 1]);
            float bound = val_of((((kl >> BSHIFT) + 1) << BSHIFT) - 1);
            if (t7 >= fmaxf(bound, 0.0f)) done = true;
        }

        #pragma unroll
        for (int u = 0; u < GROUP; u++) pa[u] = na[u];
    }

    // out[m][j][f]: j=0 is x[m][f], j=1..8 are the top values descending.
    size_t bse = (size_t)m * ((KK + 1) * FF) + f;
    out[bse]          = x[(size_t)m * FF + f];
    out[bse + 1 * FF] = t0;
    out[bse + 2 * FF] = t1;
    out[bse + 3 * FF] = t2;
    out[bse + 4 * FF] = t3;
    out[bse + 5 * FF] = t4;
    out[bse + 6 * FF] = t5;
    out[bse + 7 * FF] = t6;
    out[bse + 8 * FF] = t7;
}

extern "C" void kernel_launch(void* const* d_in, const int* in_sizes, int n_in,
                              void* d_out, int out_size) {
    const float* x   = (const float*)d_in[0];
    const float* adj = (const float*)d_in[1];
    if (n_in >= 2 && in_sizes[0] > in_sizes[1]) {  // defensive: x is the smaller input
        const float* t = x; x = adj; adj = t;
    }
    float* out = (float*)d_out;

    prep_kernel<<<FF + WARMB, 256>>>(x, adj);
    topk_kernel<<<dim3(NN / 128, FF), 128>>>(x, adj, out);
}

// round 5
// speedup vs baseline: 1.8000x; 1.8000x over previous
#include <cuda_runtime.h>

#define NN 2048
#define FF 64
#define KK 8
#define GROUP 8
#define NBUCK 4096
#define BSHIFT 20            // 32 - log2(NBUCK)
#define BPT (NBUCK / 256)    // buckets per thread in prep
#define WARMB 192            // adj L2-warm blocks

// Scratch: per-feature bucket-descending x values and node indices.
__device__ float g_sx[FF * NN];
__device__ int   g_si[FF * NN];

__device__ __forceinline__ unsigned key_of(float v) {
    unsigned u = __float_as_uint(v);
    return (u & 0x80000000u) ? ~u : (u | 0x80000000u);
}
__device__ __forceinline__ float val_of(unsigned k) {
    unsigned u = (k & 0x80000000u) ? (k ^ 0x80000000u) : ~k;
    return __uint_as_float(u);
}

// Blocks [0, FF): counting-sort feature f into descending-bucket order.
// Blocks [FF, FF+WARMB): stream-prefetch adj into L2 (runs concurrently).
__global__ __launch_bounds__(256) void prep_kernel(const float* __restrict__ x,
                                                   const float* __restrict__ adj) {
    const int tid = threadIdx.x;

    if (blockIdx.x >= FF) {
        const size_t nlines = (size_t)NN * NN * sizeof(float) / 128;
        const size_t stride = (size_t)WARMB * 256;
        for (size_t i = (size_t)(blockIdx.x - FF) * 256 + tid; i < nlines; i += stride) {
            const char* p = (const char*)adj + i * 128;
            asm volatile("prefetch.global.L2 [%0];" :: "l"(p));
        }
        return;
    }

    const int f = blockIdx.x;
    __shared__ unsigned skey[NN];
    __shared__ int hist[NBUCK];
    __shared__ int tsum[256];

    for (int i = tid; i < NBUCK; i += 256) hist[i] = 0;
    __syncthreads();

    // Pass 1: keys + histogram.
    for (int i = tid; i < NN; i += 256) {
        float v = x[(size_t)i * FF + f];
        unsigned k = key_of(v);
        skey[i] = k;
        atomicAdd(&hist[k >> BSHIFT], 1);
    }
    __syncthreads();

    // Pass 2: descending-exclusive bucket offsets (suffix scan).
    const int base = tid * BPT;
    int csum = 0;
    #pragma unroll
    for (int j = 0; j < BPT; j++) csum += hist[base + j];
    tsum[tid] = csum;
    __syncthreads();
    for (int d = 1; d < 256; d <<= 1) {     // inclusive suffix scan
        int v = tsum[tid] + ((tid + d < 256) ? tsum[tid + d] : 0);
        __syncthreads();
        tsum[tid] = v;
        __syncthreads();
    }
    int run = (tid < 255) ? tsum[tid + 1] : 0;
    #pragma unroll
    for (int j = BPT - 1; j >= 0; j--) {
        int c = hist[base + j];
        hist[base + j] = run;
        run += c;
    }
    __syncthreads();

    // Pass 3: scatter.
    for (int i = tid; i < NN; i += 256) {
        unsigned k = skey[i];
        int pos = atomicAdd(&hist[k >> BSHIFT], 1);
        g_si[f * NN + pos] = i;
        g_sx[f * NN + pos] = val_of(k);
    }
}

// blockIdx.y = f, blockIdx.x = m-tile. One thread per m (coalesced lanes).
// Walk bucket-descending rows, top-8 in registers; stop when the 8th best
// t7 >= max(bucket_upper(x_cur), 0): adj in [0,1) so every remaining product
// <= max(x, 0) < bucket upper edge. Software pipeline depth 3 (pa, pb, nc).
__global__ __launch_bounds__(256) void topk_kernel(const float* __restrict__ x,
                                                   const float* __restrict__ adj,
                                                   float* __restrict__ out) {
    __shared__ float s_x[NN + 3 * GROUP];
    __shared__ int   s_i[NN + 3 * GROUP];
    const int f = blockIdx.y;
    const int tid = threadIdx.x;
    const float NEG_INF = -__int_as_float(0x7f800000);

    for (int i = tid; i < NN; i += 256) {
        s_x[i] = g_sx[f * NN + i];
        s_i[i] = g_si[f * NN + i];
    }
    if (tid < 3 * GROUP) { s_x[NN + tid] = NEG_INF; s_i[NN + tid] = 0; }
    __syncthreads();

    const int m = blockIdx.x * 256 + tid;
    const float* adjm = adj + m;

    float t0 = NEG_INF, t1 = NEG_INF, t2 = NEG_INF, t3 = NEG_INF;
    float t4 = NEG_INF, t5 = NEG_INF, t6 = NEG_INF, t7 = NEG_INF;

    float pa[GROUP], pb[GROUP];
    #pragma unroll
    for (int u = 0; u < GROUP; u++)
        pa[u] = __ldg(adjm + (size_t)s_i[u] * NN);
    #pragma unroll
    for (int u = 0; u < GROUP; u++)
        pb[u] = __ldg(adjm + (size_t)s_i[GROUP + u] * NN);

    bool done = false;
    for (int ib = 0; ib < NN; ib += GROUP) {
        if (!__ballot_sync(0xffffffffu, !done)) break;

        // Predicated prefetch two groups ahead (done lanes issue nothing).
        float nc[GROUP];
        #pragma unroll
        for (int u = 0; u < GROUP; u++) {
            nc[u] = 0.0f;
            if (!done) nc[u] = __ldg(adjm + (size_t)s_i[ib + 2 * GROUP + u] * NN);
        }

        if (!done) {
            #pragma unroll
            for (int u = 0; u < GROUP; u++) {
                float c = pa[u] * s_x[ib + u];
                if (c > t7) {   // rare: sorted insert via max/min chain
                    float w;
                    w = fmaxf(t0, c); c = fminf(t0, c); t0 = w;
                    w = fmaxf(t1, c); c = fminf(t1, c); t1 = w;
                    w = fmaxf(t2, c); c = fminf(t2, c); t2 = w;
                    w = fmaxf(t3, c); c = fminf(t3, c); t3 = w;
                    w = fmaxf(t4, c); c = fminf(t4, c); t4 = w;
                    w = fmaxf(t5, c); c = fminf(t5, c); t5 = w;
                    w = fmaxf(t6, c); c = fminf(t6, c); t6 = w;
                    t7 = fmaxf(t7, c);
                }
            }
            // Bucket-conservative early stop.
            unsigned kl = key_of(s_x[ib + GROUP - 1]);
            float bound = val_of((((kl >> BSHIFT) + 1) << BSHIFT) - 1);
            if (t7 >= fmaxf(bound, 0.0f)) done = true;
        }

        #pragma unroll
        for (int u = 0; u < GROUP; u++) { pa[u] = pb[u]; pb[u] = nc[u]; }
    }

    // out[m][j][f]: j=0 is x[m][f], j=1..8 are the top values descending.
    size_t bse = (size_t)m * ((KK + 1) * FF) + f;
    out[bse]          = x[(size_t)m * FF + f];
    out[bse + 1 * FF] = t0;
    out[bse + 2 * FF] = t1;
    out[bse + 3 * FF] = t2;
    out[bse + 4 * FF] = t3;
    out[bse + 5 * FF] = t4;
    out[bse + 6 * FF] = t5;
    out[bse + 7 * FF] = t6;
    out[bse + 8 * FF] = t7;
}

extern "C" void kernel_launch(void* const* d_in, const int* in_sizes, int n_in,
                              void* d_out, int out_size) {
    const float* x   = (const float*)d_in[0];
    const float* adj = (const float*)d_in[1];
    if (n_in >= 2 && in_sizes[0] > in_sizes[1]) {  // defensive: x is the smaller input
        const float* t = x; x = adj; adj = t;
    }
    float* out = (float*)d_out;

    prep_kernel<<<FF + WARMB, 256>>>(x, adj);
    topk_kernel<<<dim3(NN / 256, FF), 256>>>(x, adj, out);
}

// round 8
// speedup vs baseline: 1.9110x; 1.0616x over previous
#include <cuda_runtime.h>

#define NN 2048
#define FF 64
#define KK 8
#define GROUP 8
#define NGRP (NN / GROUP)     // 256 groups of 8
#define PHA 15                // phase-A groups (120 ranks), multiple of 3
#define NBUCK 4096
#define BSHIFT 20             // 32 - log2(NBUCK)
#define BPT (NBUCK / 256)
#define WARMB 192             // adj L2-warm blocks (real loads)

// Scratch: per-feature bucket-descending (value, node-index) pairs + exact
// per-group suffix-max stop bounds.
__device__ float2 g_sp[FF * NN];
__device__ float  g_bound[FF * NGRP];
__device__ float  g_sink[1024];

__device__ __forceinline__ unsigned key_of(float v) {
    unsigned u = __float_as_uint(v);
    return (u & 0x80000000u) ? ~u : (u | 0x80000000u);
}
__device__ __forceinline__ float val_of(unsigned k) {
    unsigned u = (k & 0x80000000u) ? (k ^ 0x80000000u) : ~k;
    return __uint_as_float(u);
}

// Blocks [0, FF): counting-sort feature f into descending-bucket order and
// compute exact suffix-max bounds. Blocks [FF, FF+WARMB): pull adj into L2
// with REAL loads (prefetch.global.L2 was measurably dropped: topk re-read
// all 17MB from DRAM in R1/R2/R5).
__global__ __launch_bounds__(256) void prep_kernel(const float* __restrict__ x,
                                                   const float* __restrict__ adj) {
    const int tid = threadIdx.x;
    const float NEG_INF = -__int_as_float(0x7f800000);

    if (blockIdx.x >= FF) {
        const float4* a4 = (const float4*)adj;
        const size_t n4 = (size_t)NN * NN / 4;
        const size_t stride = (size_t)WARMB * 256;
        float s = 0.0f;
        for (size_t i = (size_t)(blockIdx.x - FF) * 256 + tid; i < n4; i += stride) {
            float4 v = __ldg(&a4[i]);
            s += v.x + v.y + v.z + v.w;
        }
        g_sink[((blockIdx.x - FF) * 256 + tid) & 1023] = s;  // defeat DCE
        return;
    }

    const int f = blockIdx.x;
    __shared__ unsigned skey[NN];
    __shared__ int hist[NBUCK];
    __shared__ float sval[NN];
    __shared__ int tsum[256];
    __shared__ float tmax[256];

    for (int i = tid; i < NBUCK; i += 256) hist[i] = 0;
    __syncthreads();

    // Pass 1: keys + histogram.
    for (int i = tid; i < NN; i += 256) {
        float v = x[(size_t)i * FF + f];
        unsigned k = key_of(v);
        skey[i] = k;
        atomicAdd(&hist[k >> BSHIFT], 1);
    }
    __syncthreads();

    // Pass 2: descending-exclusive bucket offsets (suffix scan).
    const int base = tid * BPT;
    int csum = 0;
    #pragma unroll
    for (int j = 0; j < BPT; j++) csum += hist[base + j];
    tsum[tid] = csum;
    __syncthreads();
    for (int d = 1; d < 256; d <<= 1) {
        int v = tsum[tid] + ((tid + d < 256) ? tsum[tid + d] : 0);
        __syncthreads();
        tsum[tid] = v;
        __syncthreads();
    }
    int run = (tid < 255) ? tsum[tid + 1] : 0;
    #pragma unroll
    for (int j = BPT - 1; j >= 0; j--) {
        int c = hist[base + j];
        hist[base + j] = run;
        run += c;
    }
    __syncthreads();

    // Pass 3: scatter (also keep values in smem for the bound pass).
    for (int i = tid; i < NN; i += 256) {
        unsigned k = skey[i];
        float v = val_of(k);
        int pos = atomicAdd(&hist[k >> BSHIFT], 1);
        g_sp[f * NN + pos] = make_float2(v, __int_as_float(i));
        sval[pos] = v;
    }
    __syncthreads();

    // Pass 4: exact suffix-max bounds per group of 8.
    float gm = NEG_INF;
    #pragma unroll
    for (int j = 0; j < GROUP; j++) gm = fmaxf(gm, sval[tid * GROUP + j]);
    tmax[tid] = gm;
    __syncthreads();
    for (int d = 1; d < 256; d <<= 1) {       // inclusive suffix max
        float v = fmaxf(tmax[tid], (tid + d < 256) ? tmax[tid + d] : NEG_INF);
        __syncthreads();
        tmax[tid] = v;
        __syncthreads();
    }
    // After group g, remaining products <= max(suffix_max(g+1), 0) since
    // adj in [0,1): x>0 -> adj*x <= x; x<=0 -> adj*x <= 0.
    float b = (tid < 255) ? tmax[tid + 1] : NEG_INF;
    g_bound[f * NGRP + tid] = fmaxf(b, 0.0f);
}

// blockIdx.y = f, blockIdx.x = m-tile, one thread per m (coalesced lanes).
// Phase A: first PHA groups unconditionally (extra inserts are always
// correct), 3-buffer rotation, no ballots. Phase B: branchy with exact
// suffix-max stop bound.
__global__ __launch_bounds__(256) void topk_kernel(const float* __restrict__ x,
                                                   const float* __restrict__ adj,
                                                   float* __restrict__ out) {
    __shared__ float2 s_p[NN + 48];
    __shared__ float  s_b[NGRP + 8];
    const int f = blockIdx.y;
    const int tid = threadIdx.x;
    const float NEG_INF = -__int_as_float(0x7f800000);

    #pragma unroll
    for (int i = tid; i < NN; i += 256) s_p[i] = g_sp[f * NN + i];
    if (tid < 48) s_p[NN + tid] = make_float2(NEG_INF, __int_as_float(0));
    if (tid < NGRP) s_b[tid] = g_bound[f * NGRP + tid];
    if (tid < 8) s_b[NGRP + tid] = 0.0f;
    __syncthreads();

    const int m = blockIdx.x * 256 + tid;
    const float* adjm = adj + m;

    float t[KK];
    #pragma unroll
    for (int j = 0; j < KK; j++) t[j] = NEG_INF;

    float ca[GROUP], cb[GROUP], cc[GROUP];

    // Load group g: buffer holds the PRODUCT adj[n][m] * x[n][f].
    #define LOADC(g, buf)                                                     \
        {   _Pragma("unroll")                                                 \
            for (int u = 0; u < GROUP; u++) {                                 \
                float2 p = s_p[(g) * GROUP + u];                              \
                buf[u] = __ldg(adjm + (size_t)__float_as_int(p.y) * NN) * p.x;\
            }                                                                 \
        }
    // Consume: compare + rare sorted insert (max/min chain).
    #define CONSUME(buf)                                                      \
        {   _Pragma("unroll")                                                 \
            for (int u = 0; u < GROUP; u++) {                                 \
                float c = buf[u];                                             \
                if (c > t[KK - 1]) {                                          \
                    _Pragma("unroll")                                         \
                    for (int j = 0; j < KK - 1; j++) {                        \
                        float w = fmaxf(t[j], c);                             \
                        c = fminf(t[j], c);                                   \
                        t[j] = w;                                             \
                    }                                                         \
                    t[KK - 1] = fmaxf(t[KK - 1], c);                          \
                }                                                             \
            }                                                                 \
        }

    LOADC(0, ca); LOADC(1, cb); LOADC(2, cc);

    // ---- Phase A: groups 0..PHA-1, unconditional, fully pipelined. ----
    #pragma unroll
    for (int g = 0; g < PHA; g += 3) {
        CONSUME(ca); LOADC(g + 3, ca);
        CONSUME(cb); LOADC(g + 4, cb);
        CONSUME(cc); LOADC(g + 5, cc);
    }

    // ---- Phase B: branchy scan with exact stop bound. ----
    bool done = (t[KK - 1] >= s_b[PHA - 1]);
    #pragma unroll 1
    for (int g = PHA; g < NGRP; g += 3) {
        if (!__ballot_sync(0xffffffffu, !done)) break;
        if (!done) { CONSUME(ca); done = (t[KK - 1] >= s_b[g]); }
        if (!done) LOADC(g + 3, ca);
        if (!done) { CONSUME(cb); done = (t[KK - 1] >= s_b[g + 1]); }
        if (!done) LOADC(g + 4, cb);
        if (!done) { CONSUME(cc); done = (t[KK - 1] >= s_b[g + 2]); }
        if (!done) LOADC(g + 5, cc);
    }

    // out[m][j][f]: j=0 is x[m][f], j=1..8 are the top values descending.
    size_t bse = (size_t)m * ((KK + 1) * FF) + f;
    out[bse] = x[(size_t)m * FF + f];
    #pragma unroll
    for (int j = 0; j < KK; j++) out[bse + (size_t)(j + 1) * FF] = t[j];

    #undef LOADC
    #undef CONSUME
}

extern "C" void kernel_launch(void* const* d_in, const int* in_sizes, int n_in,
                              void* d_out, int out_size) {
    const float* x   = (const float*)d_in[0];
    const float* adj = (const float*)d_in[1];
    if (n_in >= 2 && in_sizes[0] > in_sizes[1]) {  // defensive: x is the smaller input
        const float* t = x; x = adj; adj = t;
    }
    float* out = (float*)d_out;

    prep_kernel<<<FF + WARMB, 256>>>(x, adj);
    topk_kernel<<<dim3(NN / 256, FF), 256>>>(x, adj, out);
}